// round 5
// baseline (speedup 1.0000x reference)
#include <cuda_runtime.h>
#include <cstdint>

// Problem constants
#define F_ 16
#define B_ 4096
#define D_ 256
#define K_ 1024

// Scratch (device globals: allocation-free per harness rules)
__device__ float g_wt[F_ * K_ * D_];   // w transposed: [f][k][d], 16 MB
__device__ float g_wsq[F_ * K_];       // ||w_k||^2 per (f,k)
__device__ int   g_idx[F_ * B_];       // argmin codes
__device__ float g_part[8192];         // per-block loss partials

// ---------------- packed f32x2 helpers (sm_103a) ----------------
__device__ __forceinline__ void fma2(unsigned long long &c,
                                     unsigned long long a,
                                     unsigned long long b) {
    asm("fma.rn.f32x2 %0, %1, %2, %0;" : "+l"(c) : "l"(a), "l"(b));
}
__device__ __forceinline__ unsigned long long pk2(float v) {
    unsigned long long r;
    asm("mov.b64 %0, {%1, %1};" : "=l"(r) : "f"(v));
    return r;
}
__device__ __forceinline__ void upk2(unsigned long long v, float &lo, float &hi) {
    asm("mov.b64 {%0, %1}, %2;" : "=f"(lo), "=f"(hi) : "l"(v));
}
__device__ __forceinline__ void cp16(unsigned saddr, const void* g) {
    asm volatile("cp.async.cg.shared.global [%0], [%1], 16;" :: "r"(saddr), "l"(g));
}

// ---------------- kernel 1: transpose w[f][d][k] -> wt[f][k][d] ----------------
__global__ void k_transpose(const float* __restrict__ w) {
    __shared__ float t[32][33];
    const int f  = blockIdx.z;
    const int k0 = blockIdx.x * 32;
    const int d0 = blockIdx.y * 32;
    const int tx = threadIdx.x, ty = threadIdx.y;   // 32 x 8
    const float* wf = w + (size_t)f * D_ * K_;
#pragma unroll
    for (int i = 0; i < 4; i++) {
        int d = d0 + ty + i * 8;
        t[ty + i * 8][tx] = wf[(size_t)d * K_ + k0 + tx];
    }
    __syncthreads();
    float* wtf = g_wt + (size_t)f * K_ * D_;
#pragma unroll
    for (int i = 0; i < 4; i++) {
        int k = k0 + ty + i * 8;
        wtf[(size_t)k * D_ + d0 + tx] = t[tx][ty + i * 8];
    }
}

// ---------------- kernel 2: wsq[f][k] = sum_d w[f][d][k]^2 ----------------
__global__ void k_wsq(const float* __restrict__ w) {
    int t = blockIdx.x * 256 + threadIdx.x;          // 0..16383
    int f = t >> 10, k = t & (K_ - 1);
    const float* p = w + (size_t)f * D_ * K_ + k;
    float s = 0.f;
#pragma unroll 8
    for (int d = 0; d < D_; d++) {
        float v = p[(size_t)d * K_];
        s = fmaf(v, v, s);
    }
    g_wsq[t] = s;
}

// ---------------- kernel 3: fused GEMM + argmin ----------------
// Grid: (B/64, F). Block 256 threads.
// CTA tile: 64 rows x K (all 1024 cols, 4 k-tiles of 256).
// x tile (64x256 f32 = 64KB) resident in smem; w streamed in 16x256 chunks,
// double-buffered cp.async (2 x 16KB). Thread tile: 8 rows x 8 cols as 32
// f32x2 accumulators (pairs along K). Each warp covers the SAME 8 rows
// (lane spans cols) -> x smem loads are warp-uniform broadcasts.
__global__ void __launch_bounds__(256, 2)
k_main(const float* __restrict__ x, const float* __restrict__ w) {
    extern __shared__ float sm[];
    float* xs = sm;             // [64][256]
    float* ws = sm + 64 * 256;  // [2][16][256]

    const int tid  = threadIdx.x;
    const int lane = tid & 31;
    const int ty   = tid >> 5;          // warp id 0..7 -> rows ty*8..ty*8+7
    const int f    = blockIdx.y;
    const int row0 = blockIdx.x * 64;

    const float* xin = x + ((size_t)f * B_ + row0) * D_;
    const float* wf  = w + (size_t)f * D_ * K_;

    // load x tile (coalesced float4 copy, same layout as gmem)
#pragma unroll
    for (int t = 0; t < 16; t++) {
        int e = tid + t * 256;
        reinterpret_cast<float4*>(xs)[e] = reinterpret_cast<const float4*>(xin)[e];
    }

    unsigned ws_s = (unsigned)__cvta_generic_to_shared(ws);

    auto issue = [&](int cc) {
        int kt = cc >> 4, c = cc & 15, buf = cc & 1;
        const float* g0 = wf + (size_t)(c * 16) * K_ + kt * 256;
        unsigned sb = ws_s + (unsigned)buf * 16384u;
#pragma unroll
        for (int t = 0; t < 4; t++) {
            int e  = tid + t * 256;      // 0..1023 float4s
            int dc = e >> 6, cg = e & 63;
            cp16(sb + (unsigned)(dc * 1024 + cg * 16), g0 + (size_t)dc * K_ + cg * 4);
        }
        asm volatile("cp.async.commit_group;");
    };

    issue(0);

    float bestv[8];
    int   besti[8];
#pragma unroll
    for (int r = 0; r < 8; r++) { bestv[r] = 3.4e38f; besti[r] = 0; }

    for (int kt = 0; kt < 4; kt++) {
        unsigned long long acc[8][4];
#pragma unroll
        for (int r = 0; r < 8; r++)
#pragma unroll
            for (int j = 0; j < 4; j++) acc[r][j] = 0ull;

        for (int c = 0; c < 16; c++) {
            int cc = kt * 16 + c;
            if (cc + 1 < 64) { issue(cc + 1); asm volatile("cp.async.wait_group 1;"); }
            else             { asm volatile("cp.async.wait_group 0;"); }
            __syncthreads();

            const float* wsb = ws + (cc & 1) * 4096;
            const float* xr  = xs + ty * 8 * 256 + c * 16;

#pragma unroll
            for (int dd2 = 0; dd2 < 8; dd2++) {
                float2 a2[8];
#pragma unroll
                for (int r = 0; r < 8; r++)
                    a2[r] = *reinterpret_cast<const float2*>(xr + r * 256 + dd2 * 2);
#pragma unroll
                for (int s = 0; s < 2; s++) {
                    const float* brow = wsb + (dd2 * 2 + s) * 256 + lane * 8;
                    ulonglong2 b01 = *reinterpret_cast<const ulonglong2*>(brow);
                    ulonglong2 b23 = *reinterpret_cast<const ulonglong2*>(brow + 4);
#pragma unroll
                    for (int r = 0; r < 8; r++) {
                        unsigned long long ap = pk2(s == 0 ? a2[r].x : a2[r].y);
                        fma2(acc[r][0], ap, b01.x);
                        fma2(acc[r][1], ap, b01.y);
                        fma2(acc[r][2], ap, b23.x);
                        fma2(acc[r][3], ap, b23.y);
                    }
                }
            }
            __syncthreads();
        }

        // scores + argmin for this k-tile (score = ||w||^2 - 2 x.w ; x^2 constant)
        float wsqv[8];
#pragma unroll
        for (int j = 0; j < 8; j++)
            wsqv[j] = __ldg(&g_wsq[f * K_ + kt * 256 + lane * 8 + j]);

#pragma unroll
        for (int r = 0; r < 8; r++) {
            float lv = 3.4e38f; int li = 0;
#pragma unroll
            for (int jp = 0; jp < 4; jp++) {
                float x0, x1;
                upk2(acc[r][jp], x0, x1);
                float v0 = fmaf(-2.f, x0, wsqv[jp * 2]);
                float v1 = fmaf(-2.f, x1, wsqv[jp * 2 + 1]);
                int c0 = lane * 8 + jp * 2;                 // ascending -> strict <
                if (v0 < lv) { lv = v0; li = c0; }          //   keeps lowest index
                if (v1 < lv) { lv = v1; li = c0 + 1; }
            }
            // warp butterfly: lexicographic (value, index) min == jnp.argmin tie rule
#pragma unroll
            for (int off = 16; off >= 1; off >>= 1) {
                float ov = __shfl_xor_sync(0xffffffffu, lv, off);
                int   oi = __shfl_xor_sync(0xffffffffu, li, off);
                if (ov < lv || (ov == lv && oi < li)) { lv = ov; li = oi; }
            }
            int gk = kt * 256 + li;
            if (lv < bestv[r]) { bestv[r] = lv; besti[r] = gk; }  // strict < : earlier kt wins ties
        }
    }

    if (lane == 0) {
#pragma unroll
        for (int r = 0; r < 8; r++)
            g_idx[f * B_ + row0 + ty * 8 + r] = besti[r];
    }
}

// ---------------- kernel 4: gather + straight-through output + loss partials ----------------
__global__ void k_gather(const float* __restrict__ x, float* __restrict__ out) {
    __shared__ float red[256];
    const int tid  = threadIdx.x;
    const int lane = tid & 31;
    const int wid  = tid >> 5;
    const int row  = blockIdx.x * 8 + wid;           // < 65536 = F*B
    const int f    = row >> 12;                      // /B_
    const int idx  = g_idx[row];

    const float4* q4 = reinterpret_cast<const float4*>(g_wt + (size_t)(f * K_ + idx) * D_);
    const float4* x4 = reinterpret_cast<const float4*>(x + (size_t)row * D_);
    float4*       o4 = reinterpret_cast<float4*>(out + (size_t)row * D_);

    float ls = 0.f;
#pragma unroll
    for (int t = 0; t < 2; t++) {
        int e = lane + t * 32;
        float4 q = q4[e], xv = x4[e];
        float d0 = q.x - xv.x, d1 = q.y - xv.y, d2 = q.z - xv.z, d3 = q.w - xv.w;
        // output = x + stopgrad(q - x)  (same fp expression as reference)
        float4 ov;
        ov.x = xv.x + d0; ov.y = xv.y + d1; ov.z = xv.z + d2; ov.w = xv.w + d3;
        o4[e] = ov;
        ls += d0 * d0 + d1 * d1 + d2 * d2 + d3 * d3;
    }
    red[tid] = ls;
    __syncthreads();
    for (int s = 128; s > 0; s >>= 1) {
        if (tid < s) red[tid] += red[tid + s];
        __syncthreads();
    }
    if (tid == 0) g_part[blockIdx.x] = red[0];
}

// ---------------- kernel 5: deterministic final loss reduction ----------------
__global__ void k_loss(float* __restrict__ out) {
    __shared__ float red[256];
    const int tid = threadIdx.x;
    float s = 0.f;
#pragma unroll
    for (int i = 0; i < 32; i++) s += g_part[tid + 256 * i];
    red[tid] = s;
    __syncthreads();
    for (int st = 128; st > 0; st >>= 1) {
        if (tid < st) red[tid] += red[tid + st];
        __syncthreads();
    }
    if (tid == 0)
        out[(size_t)F_ * B_ * D_] = red[0] * (0.25f / (float)(F_ * B_ * D_));
}

extern "C" void kernel_launch(void* const* d_in, const int* in_sizes, int n_in,
                              void* d_out, int out_size) {
    const float* x = (const float*)d_in[0];   // [F,B,D] fp32
    const float* w = (const float*)d_in[1];   // [F,D,K] fp32
    float* out = (float*)d_out;               // [F*B*D] output + 1 loss scalar

    (void)in_sizes; (void)n_in; (void)out_size;

    k_transpose<<<dim3(K_ / 32, D_ / 32, F_), dim3(32, 8)>>>(w);
    k_wsq<<<(F_ * K_) / 256, 256>>>(w);

    cudaFuncSetAttribute(k_main, cudaFuncAttributeMaxDynamicSharedMemorySize, 98304);
    k_main<<<dim3(B_ / 64, F_), 256, 98304>>>(x, w);

    k_gather<<<(F_ * B_) / 8, 256>>>(x, out);
    k_loss<<<1, 256>>>(out);
}

// round 8
// speedup vs baseline: 2.2523x; 2.2523x over previous
#include <cuda_runtime.h>
#include <cuda_bf16.h>
#include <cstdint>

#define F_ 16
#define B_ 4096
#define D_ 256
#define K_ 1024

// ---------------- device scratch (allocation-free) ----------------
__device__ __align__(128) float         g_wt [F_ * K_ * D_];   // w^T fp32 [f][k][d]
__device__ __align__(128) __nv_bfloat16 g_wtb[F_ * K_ * D_];   // w^T bf16 [f][k][d]
__device__ __align__(128) __nv_bfloat16 g_xb [F_ * B_ * D_];   // x bf16   [f][b][d]
__device__ float g_wsq [F_ * K_];          // ||w_k||^2
__device__ float g_cval[F_ * B_ * 12];     // screened candidate scores
__device__ int   g_cidx[F_ * B_ * 12];     // screened candidate indices
__device__ float g_part[8192];             // loss partials

// ---------------- PTX helpers ----------------
__device__ __forceinline__ uint32_t sm_u32(const void* p) {
    uint32_t a;
    asm("{ .reg .u64 t; cvta.to.shared.u64 t, %1; cvt.u32.u64 %0, t; }" : "=r"(a) : "l"(p));
    return a;
}
__device__ __forceinline__ void cp16(uint32_t saddr, const void* g) {
    asm volatile("cp.async.cg.shared.global [%0], [%1], 16;" :: "r"(saddr), "l"(g));
}
__device__ __forceinline__ void ldsm4(uint32_t* r, uint32_t a) {
    asm volatile("ldmatrix.sync.aligned.m8n8.x4.shared.b16 {%0,%1,%2,%3}, [%4];"
                 : "=r"(r[0]), "=r"(r[1]), "=r"(r[2]), "=r"(r[3]) : "r"(a));
}
__device__ __forceinline__ void mma16816(float* c, const uint32_t* a, const uint32_t* b) {
    asm volatile(
        "mma.sync.aligned.m16n8k16.row.col.f32.bf16.bf16.f32 "
        "{%0,%1,%2,%3}, {%4,%5,%6,%7}, {%8,%9}, {%0,%1,%2,%3};"
        : "+f"(c[0]), "+f"(c[1]), "+f"(c[2]), "+f"(c[3])
        : "r"(a[0]), "r"(a[1]), "r"(a[2]), "r"(a[3]), "r"(b[0]), "r"(b[1]));
}
// lexicographic (value, index) top-3 insert == jnp.argmin first-index tie rule
__device__ __forceinline__ void ins3(float v, int id,
                                     float& t0, float& t1, float& t2,
                                     int& i0, int& i1, int& i2) {
    if (v < t0 || (v == t0 && id < i0))      { t2 = t1; i2 = i1; t1 = t0; i1 = i0; t0 = v; i0 = id; }
    else if (v < t1 || (v == t1 && id < i1)) { t2 = t1; i2 = i1; t1 = v;  i1 = id; }
    else if (v < t2 || (v == t2 && id < i2)) { t2 = v;  i2 = id; }
}

// ---------------- kernel 1: x -> bf16 ----------------
__global__ void k_xbf(const float* __restrict__ x) {
    int i = blockIdx.x * 256 + threadIdx.x;
    float4 v = reinterpret_cast<const float4*>(x)[i];
    __nv_bfloat162 h0 = __floats2bfloat162_rn(v.x, v.y);
    __nv_bfloat162 h1 = __floats2bfloat162_rn(v.z, v.w);
    uint2 u;
    u.x = *reinterpret_cast<uint32_t*>(&h0);
    u.y = *reinterpret_cast<uint32_t*>(&h1);
    reinterpret_cast<uint2*>(g_xb)[i] = u;
}

// ---------------- kernel 2: transpose w[f][d][k] -> wt (fp32 + bf16) ----------------
__global__ void k_transpose(const float* __restrict__ w) {
    __shared__ float t[32][33];
    const int f = blockIdx.z, k0 = blockIdx.x * 32, d0 = blockIdx.y * 32;
    const int tx = threadIdx.x, ty = threadIdx.y;   // 32 x 8
    const float* wf = w + (size_t)f * D_ * K_;
#pragma unroll
    for (int i = 0; i < 4; i++) {
        int d = d0 + ty + i * 8;
        t[ty + i * 8][tx] = wf[(size_t)d * K_ + k0 + tx];
    }
    __syncthreads();
    float*         wtf  = g_wt  + (size_t)f * K_ * D_;
    __nv_bfloat16* wtbf = g_wtb + (size_t)f * K_ * D_;
#pragma unroll
    for (int i = 0; i < 4; i++) {
        int k = k0 + ty + i * 8;
        float v = t[tx][ty + i * 8];
        wtf [(size_t)k * D_ + d0 + tx] = v;
        wtbf[(size_t)k * D_ + d0 + tx] = __float2bfloat16(v);
    }
}

// ---------------- kernel 3: wsq ----------------
__global__ void k_wsq(const float* __restrict__ w) {
    int t = blockIdx.x * 256 + threadIdx.x;
    int f = t >> 10, k = t & (K_ - 1);
    const float* p = w + (size_t)f * D_ * K_ + k;
    float s = 0.f;
#pragma unroll 8
    for (int d = 0; d < D_; d++) {
        float v = p[(size_t)d * K_];
        s = fmaf(v, v, s);
    }
    g_wsq[t] = s;
}

// ---------------- kernel 4: bf16 mma.sync screen, top-3 per 256-code tile ----------------
// Grid (B/128, K/256, F). Block 512 (16 warps, 4x4 warp grid, warp tile 32x64).
// S[128][256] over K=D=256, streamed in 4 d-chunks of 64 (double-buffered cp.async).
// SMEM rows are 128B; swizzle: addr = r*128 + (colByte ^ ((r&7)<<4)).
__global__ void __launch_bounds__(512, 1) k_screen() {
    extern __shared__ __align__(128) char dsm[];
    __shared__ float s_wsq[256];
    __shared__ float s_tv[128][12];
    __shared__ int   s_ti[128][12];

    const int tid = threadIdx.x, lane = tid & 31, wid = tid >> 5;
    const int wm = wid >> 2, wn = wid & 3;
    const int g = lane >> 2, tg = lane & 3;
    const int f = blockIdx.z, kt = blockIdx.y, row0 = blockIdx.x * 128;

    const uint32_t aS = (sm_u32(dsm) + 1023u) & ~1023u;   // [2][128 rows][64 d] bf16
    const uint32_t bS = aS + 32768u;                      // [2][256 codes][64 d] bf16

    if (tid < 256) s_wsq[tid] = g_wsq[f * K_ + kt * 256 + tid];

    const char* xg = (const char*)g_xb  + (size_t)(f * B_ + row0)      * 512;
    const char* wg = (const char*)g_wtb + (size_t)(f * K_ + kt * 256)  * 512;

    auto issue = [&](int c) {
        uint32_t ab = aS + (uint32_t)(c & 1) * 16384u;
        uint32_t bb = bS + (uint32_t)(c & 1) * 32768u;
#pragma unroll
        for (int i = 0; i < 2; i++) {                    // A: 1024 x 16B
            int t = tid + i * 512, r = t >> 3, cc = t & 7;
            cp16(ab + (uint32_t)(r * 128 + ((cc * 16) ^ ((r & 7) << 4))),
                 xg + (size_t)r * 512 + c * 128 + cc * 16);
        }
#pragma unroll
        for (int i = 0; i < 4; i++) {                    // B: 2048 x 16B
            int t = tid + i * 512, r = t >> 3, cc = t & 7;
            cp16(bb + (uint32_t)(r * 128 + ((cc * 16) ^ ((r & 7) << 4))),
                 wg + (size_t)r * 512 + c * 128 + cc * 16);
        }
        asm volatile("cp.async.commit_group;");
    };

    issue(0);
    issue(1);

    // per-lane ldmatrix constants: row base, row swizzle, lane column byte.
    // Load addr = base + rowBase + ((klb + laneCol) ^ rowSw)   [disjoint bits in +]
    uint32_t aBase[2], aSw[2], bBase[4], bSw[4];
    const uint32_t aCol = (uint32_t)((lane >> 4) << 4);          // 0 | 16
    const uint32_t bCol = (uint32_t)(((lane >> 3) & 1) << 4);    // 0 | 16
#pragma unroll
    for (int mt = 0; mt < 2; mt++) {
        int r = wm * 32 + mt * 16 + (lane & 15);
        aBase[mt] = (uint32_t)(r * 128);
        aSw[mt]   = (uint32_t)((r & 7) << 4);
    }
#pragma unroll
    for (int nt2 = 0; nt2 < 4; nt2++) {
        int r = wn * 64 + nt2 * 16 + (lane & 7) + ((lane >> 4) << 3);
        bBase[nt2] = (uint32_t)(r * 128);
        bSw[nt2]   = (uint32_t)((r & 7) << 4);
    }

    float acc[2][8][4];
#pragma unroll
    for (int mt = 0; mt < 2; mt++)
#pragma unroll
        for (int nt = 0; nt < 8; nt++)
#pragma unroll
            for (int j = 0; j < 4; j++) acc[mt][nt][j] = 0.f;

    for (int c = 0; c < 4; c++) {
        if (c == 3) asm volatile("cp.async.wait_group 0;");
        else        asm volatile("cp.async.wait_group 1;");
        __syncthreads();
        uint32_t ab = aS + (uint32_t)(c & 1) * 16384u;
        uint32_t bb = bS + (uint32_t)(c & 1) * 32768u;
#pragma unroll
        for (int ks = 0; ks < 4; ks++) {
            uint32_t klb = (uint32_t)(ks * 32);          // k-step * 16 elems * 2B
            uint32_t a[2][4], b[4][4];
#pragma unroll
            for (int mt = 0; mt < 2; mt++)
                ldsm4(a[mt], ab + aBase[mt] + ((klb + aCol) ^ aSw[mt]));
#pragma unroll
            for (int nt2 = 0; nt2 < 4; nt2++)
                ldsm4(b[nt2], bb + bBase[nt2] + ((klb + bCol) ^ bSw[nt2]));
#pragma unroll
            for (int mt = 0; mt < 2; mt++)
#pragma unroll
                for (int nt2 = 0; nt2 < 4; nt2++) {
                    mma16816(acc[mt][nt2 * 2],     a[mt], &b[nt2][0]);
                    mma16816(acc[mt][nt2 * 2 + 1], a[mt], &b[nt2][2]);
                }
        }
        __syncthreads();
        if (c + 2 < 4) issue(c + 2);
    }

    // Epilogue: v = wsq - 2*xw ; per-row top-3 within this 256-code tile.
#pragma unroll
    for (int mt = 0; mt < 2; mt++)
#pragma unroll
        for (int h = 0; h < 2; h++) {
            float t0 = 3.4e38f, t1 = 3.4e38f, t2 = 3.4e38f;
            int   i0 = 0, i1 = 0, i2 = 0;
#pragma unroll
            for (int nt = 0; nt < 8; nt++)
#pragma unroll
                for (int e = 0; e < 2; e++) {
                    int cl = wn * 64 + nt * 8 + tg * 2 + e;
                    float v = fmaf(-2.f, acc[mt][nt][h * 2 + e], s_wsq[cl]);
                    ins3(v, kt * 256 + cl, t0, t1, t2, i0, i1, i2);
                }
#pragma unroll
            for (int off = 1; off <= 2; off <<= 1) {     // merge across 4-lane quad
                float o0 = __shfl_xor_sync(~0u, t0, off);
                float o1 = __shfl_xor_sync(~0u, t1, off);
                float o2 = __shfl_xor_sync(~0u, t2, off);
                int   a0 = __shfl_xor_sync(~0u, i0, off);
                int   a1 = __shfl_xor_sync(~0u, i1, off);
                int   a2 = __shfl_xor_sync(~0u, i2, off);
                ins3(o0, a0, t0, t1, t2, i0, i1, i2);
                ins3(o1, a1, t0, t1, t2, i0, i1, i2);
                ins3(o2, a2, t0, t1, t2, i0, i1, i2);
            }
            if (tg == 0) {
                int rl = wm * 32 + mt * 16 + g + h * 8;
                s_tv[rl][wn * 3]     = t0; s_ti[rl][wn * 3]     = i0;
                s_tv[rl][wn * 3 + 1] = t1; s_ti[rl][wn * 3 + 1] = i1;
                s_tv[rl][wn * 3 + 2] = t2; s_ti[rl][wn * 3 + 2] = i2;
            }
        }
    __syncthreads();

    if (tid < 128) {
        float t0 = 3.4e38f, t1 = 3.4e38f, t2 = 3.4e38f;
        int   i0 = 0, i1 = 0, i2 = 0;
#pragma unroll
        for (int j = 0; j < 12; j++) ins3(s_tv[tid][j], s_ti[tid][j], t0, t1, t2, i0, i1, i2);
        int row = f * B_ + row0 + tid;
        int b = row * 12 + kt * 3;
        g_cval[b] = t0; g_cval[b + 1] = t1; g_cval[b + 2] = t2;
        g_cidx[b] = i0; g_cidx[b + 1] = i1; g_cidx[b + 2] = i2;
    }
}

// ---------------- kernel 5: exact rescore + straight-through out + loss ----------------
__global__ void __launch_bounds__(256) k_rescore(const float* __restrict__ x,
                                                 float* __restrict__ out) {
    __shared__ float red[8];
    const int tid = threadIdx.x, lane = tid & 31, wid = tid >> 5;
    const int row = blockIdx.x * 8 + wid;
    const int f = row >> 12;

    float cv = 3.4e38f; int ci = 0;
    if (lane < 12) { cv = g_cval[row * 12 + lane]; ci = g_cidx[row * 12 + lane]; }
    float minv = cv;
#pragma unroll
    for (int o = 16; o >= 1; o >>= 1) minv = fminf(minv, __shfl_xor_sync(~0u, minv, o));
    const float gate = minv + 0.05f;   // ~10 sigma of bf16 screen error

    const float4* x4 = reinterpret_cast<const float4*>(x + (size_t)row * D_);
    const float4 xa = x4[lane], xb2 = x4[lane + 32];

    float bs = 3.4e38f; int bi = 0;
#pragma unroll 1
    for (int j = 0; j < 12; j++) {
        float vj = __shfl_sync(~0u, cv, j);
        int   ij = __shfl_sync(~0u, ci, j);
        if (vj <= gate) {                       // warp-uniform
            const float4* q4 = reinterpret_cast<const float4*>(g_wt + (size_t)(f * K_ + ij) * D_);
            float4 qa = q4[lane], qb = q4[lane + 32];
            float p = xa.x * qa.x;
            p = fmaf(xa.y, qa.y, p);  p = fmaf(xa.z, qa.z, p);  p = fmaf(xa.w, qa.w, p);
            p = fmaf(xb2.x, qb.x, p); p = fmaf(xb2.y, qb.y, p);
            p = fmaf(xb2.z, qb.z, p); p = fmaf(xb2.w, qb.w, p);
#pragma unroll
            for (int o = 16; o >= 1; o >>= 1) p += __shfl_xor_sync(~0u, p, o);
            float s = fmaf(-2.f, p, g_wsq[f * K_ + ij]);
            if (s < bs || (s == bs && ij < bi)) { bs = s; bi = ij; }   // first-index tie rule
        }
    }

    const float4* q4 = reinterpret_cast<const float4*>(g_wt + (size_t)(f * K_ + bi) * D_);
    float ls = 0.f;
    {
        float4 q = q4[lane];
        float d0 = q.x - xa.x, d1 = q.y - xa.y, d2 = q.z - xa.z, d3 = q.w - xa.w;
        float4 o; o.x = xa.x + d0; o.y = xa.y + d1; o.z = xa.z + d2; o.w = xa.w + d3;
        reinterpret_cast<float4*>(out)[(size_t)row * 64 + lane] = o;
        ls += d0 * d0 + d1 * d1 + d2 * d2 + d3 * d3;
    }
    {
        float4 q = q4[lane + 32];
        float d0 = q.x - xb2.x, d1 = q.y - xb2.y, d2 = q.z - xb2.z, d3 = q.w - xb2.w;
        float4 o; o.x = xb2.x + d0; o.y = xb2.y + d1; o.z = xb2.z + d2; o.w = xb2.w + d3;
        reinterpret_cast<float4*>(out)[(size_t)row * 64 + lane + 32] = o;
        ls += d0 * d0 + d1 * d1 + d2 * d2 + d3 * d3;
    }
#pragma unroll
    for (int o = 16; o >= 1; o >>= 1) ls += __shfl_xor_sync(~0u, ls, o);
    if (lane == 0) red[wid] = ls;
    __syncthreads();
    if (tid == 0) {
        float s = 0.f;
#pragma unroll
        for (int i = 0; i < 8; i++) s += red[i];
        g_part[blockIdx.x] = s;
    }
}

// ---------------- kernel 6: deterministic final loss ----------------
__global__ void k_loss(float* __restrict__ out) {
    __shared__ float red[256];
    const int tid = threadIdx.x;
    float s = 0.f;
#pragma unroll
    for (int i = 0; i < 32; i++) s += g_part[tid + 256 * i];
    red[tid] = s;
    __syncthreads();
    for (int st = 128; st > 0; st >>= 1) {
        if (tid < st) red[tid] += red[tid + st];
        __syncthreads();
    }
    if (tid == 0)
        out[(size_t)F_ * B_ * D_] = red[0] * (0.25f / (float)(F_ * B_ * D_));
}

extern "C" void kernel_launch(void* const* d_in, const int* in_sizes, int n_in,
                              void* d_out, int out_size) {
    const float* x = (const float*)d_in[0];   // [F,B,D] fp32
    const float* w = (const float*)d_in[1];   // [F,D,K] fp32
    float* out = (float*)d_out;
    (void)in_sizes; (void)n_in; (void)out_size;

    k_xbf<<<(F_ * B_ * D_) / 4 / 256, 256>>>(x);
    k_transpose<<<dim3(K_ / 32, D_ / 32, F_), dim3(32, 8)>>>(w);
    k_wsq<<<(F_ * K_) / 256, 256>>>(w);

    cudaFuncSetAttribute(k_screen, cudaFuncAttributeMaxDynamicSharedMemorySize, 99328);
    k_screen<<<dim3(B_ / 128, K_ / 256, F_), 512, 99328>>>();

    k_rescore<<<(F_ * B_) / 8, 256>>>(x, out);
    k_loss<<<1, 256>>>(out);
}

// round 10
// speedup vs baseline: 2.4784x; 1.1004x over previous
#include <cuda_runtime.h>
#include <cuda_bf16.h>
#include <cstdint>

#define F_ 16
#define B_ 4096
#define D_ 256
#define K_ 1024

// ---------------- device scratch (allocation-free) ----------------
__device__ __align__(128) float         g_wt [F_ * K_ * D_];   // w^T fp32 [f][k][d]
__device__ __align__(128) __nv_bfloat16 g_wtb[F_ * K_ * D_];   // w^T bf16 [f][k][d]
__device__ __align__(128) __nv_bfloat16 g_xb [F_ * B_ * D_];   // x bf16   [f][b][d]
__device__ float g_wsq [F_ * K_];          // ||w_k||^2
__device__ float g_cval[F_ * B_ * 24];     // screened candidate scores
__device__ int   g_cidx[F_ * B_ * 24];     // screened candidate indices
__device__ float g_part[8192];             // loss partials

// ---------------- PTX helpers ----------------
__device__ __forceinline__ uint32_t sm_u32(const void* p) {
    uint32_t a;
    asm("{ .reg .u64 t; cvta.to.shared.u64 t, %1; cvt.u32.u64 %0, t; }" : "=r"(a) : "l"(p));
    return a;
}
__device__ __forceinline__ void cp16(uint32_t saddr, const void* g) {
    asm volatile("cp.async.cg.shared.global [%0], [%1], 16;" :: "r"(saddr), "l"(g));
}
__device__ __forceinline__ void ldsm4(uint32_t* r, uint32_t a) {
    asm volatile("ldmatrix.sync.aligned.m8n8.x4.shared.b16 {%0,%1,%2,%3}, [%4];"
                 : "=r"(r[0]), "=r"(r[1]), "=r"(r[2]), "=r"(r[3]) : "r"(a));
}
__device__ __forceinline__ void mma16816(float* c, const uint32_t* a, const uint32_t* b) {
    asm volatile(
        "mma.sync.aligned.m16n8k16.row.col.f32.bf16.bf16.f32 "
        "{%0,%1,%2,%3}, {%4,%5,%6,%7}, {%8,%9}, {%0,%1,%2,%3};"
        : "+f"(c[0]), "+f"(c[1]), "+f"(c[2]), "+f"(c[3])
        : "r"(a[0]), "r"(a[1]), "r"(a[2]), "r"(a[3]), "r"(b[0]), "r"(b[1]));
}
// lexicographic (value, index) top-3 insert == jnp.argmin first-index tie rule
__device__ __forceinline__ void ins3(float v, int id,
                                     float& t0, float& t1, float& t2,
                                     int& i0, int& i1, int& i2) {
    if (v < t0 || (v == t0 && id < i0))      { t2 = t1; i2 = i1; t1 = t0; i1 = i0; t0 = v; i0 = id; }
    else if (v < t1 || (v == t1 && id < i1)) { t2 = t1; i2 = i1; t1 = v;  i1 = id; }
    else if (v < t2 || (v == t2 && id < i2)) { t2 = v;  i2 = id; }
}

// ---------------- kernel 1: x -> bf16 ----------------
__global__ void k_xbf(const float* __restrict__ x) {
    int i = blockIdx.x * 256 + threadIdx.x;
    float4 v = reinterpret_cast<const float4*>(x)[i];
    __nv_bfloat162 h0 = __floats2bfloat162_rn(v.x, v.y);
    __nv_bfloat162 h1 = __floats2bfloat162_rn(v.z, v.w);
    uint2 u;
    u.x = *reinterpret_cast<uint32_t*>(&h0);
    u.y = *reinterpret_cast<uint32_t*>(&h1);
    reinterpret_cast<uint2*>(g_xb)[i] = u;
}

// ---------------- kernel 2: transpose w[f][d][k] -> wt (fp32 + bf16) ----------------
__global__ void k_transpose(const float* __restrict__ w) {
    __shared__ float t[32][33];
    const int f = blockIdx.z, k0 = blockIdx.x * 32, d0 = blockIdx.y * 32;
    const int tx = threadIdx.x, ty = threadIdx.y;   // 32 x 8
    const float* wf = w + (size_t)f * D_ * K_;
#pragma unroll
    for (int i = 0; i < 4; i++) {
        int d = d0 + ty + i * 8;
        t[ty + i * 8][tx] = wf[(size_t)d * K_ + k0 + tx];
    }
    __syncthreads();
    float*         wtf  = g_wt  + (size_t)f * K_ * D_;
    __nv_bfloat16* wtbf = g_wtb + (size_t)f * K_ * D_;
#pragma unroll
    for (int i = 0; i < 4; i++) {
        int k = k0 + ty + i * 8;
        float v = t[tx][ty + i * 8];
        wtf [(size_t)k * D_ + d0 + tx] = v;
        wtbf[(size_t)k * D_ + d0 + tx] = __float2bfloat16(v);
    }
}

// ---------------- kernel 3: wsq ----------------
__global__ void k_wsq(const float* __restrict__ w) {
    int t = blockIdx.x * 256 + threadIdx.x;
    int f = t >> 10, k = t & (K_ - 1);
    const float* p = w + (size_t)f * D_ * K_ + k;
    float s = 0.f;
#pragma unroll 8
    for (int d = 0; d < D_; d++) {
        float v = p[(size_t)d * K_];
        s = fmaf(v, v, s);
    }
    g_wsq[t] = s;
}

// ---------------- kernel 4: bf16 mma.sync screen, top-3 per 128-code tile ----------------
// Grid (B/128, K/128, F) = (32, 8, 16). Block 256 (8 warps, 4x2 grid, warp tile
// 32x64). 2 CTAs/SM (regs 128, smem 64KB) -> two independent barrier domains
// per SM so one CTA's HMMAs cover the other's cp.async/sync/epilogue stalls.
// S[128 rows][128 codes] over K=D=256, streamed in 4 d-chunks of 64.
// SMEM rows are 128B; swizzle: addr = r*128 + (colByte ^ ((r&7)<<4)).
__global__ void __launch_bounds__(256, 2) k_screen() {
    extern __shared__ __align__(128) char dsm[];
    __shared__ float s_wsq[128];
    __shared__ float s_tv[128][6];
    __shared__ int   s_ti[128][6];

    const int tid = threadIdx.x, lane = tid & 31, wid = tid >> 5;
    const int wm = wid >> 1, wn = wid & 1;
    const int g = lane >> 2, tg = lane & 3;
    const int f = blockIdx.z, kt = blockIdx.y, row0 = blockIdx.x * 128;

    const uint32_t aS = (sm_u32(dsm) + 1023u) & ~1023u;   // [2][128 rows][64 d] bf16
    const uint32_t bS = aS + 32768u;                      // [2][128 codes][64 d] bf16

    if (tid < 128) s_wsq[tid] = g_wsq[f * K_ + kt * 128 + tid];

    const char* xg = (const char*)g_xb  + (size_t)(f * B_ + row0)      * 512;
    const char* wg = (const char*)g_wtb + (size_t)(f * K_ + kt * 128)  * 512;

    auto issue = [&](int c) {
        uint32_t ab = aS + (uint32_t)(c & 1) * 16384u;
        uint32_t bb = bS + (uint32_t)(c & 1) * 16384u;
#pragma unroll
        for (int i = 0; i < 4; i++) {                    // A: 1024 x 16B
            int t = tid + i * 256, r = t >> 3, cc = t & 7;
            cp16(ab + (uint32_t)(r * 128 + ((cc * 16) ^ ((r & 7) << 4))),
                 xg + (size_t)r * 512 + c * 128 + cc * 16);
        }
#pragma unroll
        for (int i = 0; i < 4; i++) {                    // B: 1024 x 16B
            int t = tid + i * 256, r = t >> 3, cc = t & 7;
            cp16(bb + (uint32_t)(r * 128 + ((cc * 16) ^ ((r & 7) << 4))),
                 wg + (size_t)r * 512 + c * 128 + cc * 16);
        }
        asm volatile("cp.async.commit_group;");
    };

    issue(0);
    issue(1);

    // per-lane ldmatrix constants: row base, row swizzle, lane column byte.
    // Load addr = base + rowBase + ((klb + laneCol) ^ rowSw)   [disjoint bits in +]
    uint32_t aBase[2], aSw[2], bBase[4], bSw[4];
    const uint32_t aCol = (uint32_t)((lane >> 4) << 4);          // 0 | 16
    const uint32_t bCol = (uint32_t)(((lane >> 3) & 1) << 4);    // 0 | 16
#pragma unroll
    for (int mt = 0; mt < 2; mt++) {
        int r = wm * 32 + mt * 16 + (lane & 15);
        aBase[mt] = (uint32_t)(r * 128);
        aSw[mt]   = (uint32_t)((r & 7) << 4);
    }
#pragma unroll
    for (int nt2 = 0; nt2 < 4; nt2++) {
        int r = wn * 64 + nt2 * 16 + (lane & 7) + ((lane >> 4) << 3);
        bBase[nt2] = (uint32_t)(r * 128);
        bSw[nt2]   = (uint32_t)((r & 7) << 4);
    }

    float acc[2][8][4];
#pragma unroll
    for (int mt = 0; mt < 2; mt++)
#pragma unroll
        for (int nt = 0; nt < 8; nt++)
#pragma unroll
            for (int j = 0; j < 4; j++) acc[mt][nt][j] = 0.f;

    for (int c = 0; c < 4; c++) {
        if (c == 3) asm volatile("cp.async.wait_group 0;");
        else        asm volatile("cp.async.wait_group 1;");
        __syncthreads();
        uint32_t ab = aS + (uint32_t)(c & 1) * 16384u;
        uint32_t bb = bS + (uint32_t)(c & 1) * 16384u;
#pragma unroll
        for (int ks = 0; ks < 4; ks++) {
            uint32_t klb = (uint32_t)(ks * 32);          // k-step * 16 elems * 2B
            uint32_t a[2][4], b[4][4];
#pragma unroll
            for (int mt = 0; mt < 2; mt++)
                ldsm4(a[mt], ab + aBase[mt] + ((klb + aCol) ^ aSw[mt]));
#pragma unroll
            for (int nt2 = 0; nt2 < 4; nt2++)
                ldsm4(b[nt2], bb + bBase[nt2] + ((klb + bCol) ^ bSw[nt2]));
#pragma unroll
            for (int mt = 0; mt < 2; mt++)
#pragma unroll
                for (int nt2 = 0; nt2 < 4; nt2++) {
                    mma16816(acc[mt][nt2 * 2],     a[mt], &b[nt2][0]);
                    mma16816(acc[mt][nt2 * 2 + 1], a[mt], &b[nt2][2]);
                }
        }
        __syncthreads();
        if (c + 2 < 4) issue(c + 2);
    }

    // Epilogue: v = wsq - 2*xw ; per-row top-3 within this 128-code tile.
#pragma unroll
    for (int mt = 0; mt < 2; mt++)
#pragma unroll
        for (int h = 0; h < 2; h++) {
            float t0 = 3.4e38f, t1 = 3.4e38f, t2 = 3.4e38f;
            int   i0 = 0, i1 = 0, i2 = 0;
#pragma unroll
            for (int nt = 0; nt < 8; nt++)
#pragma unroll
                for (int e = 0; e < 2; e++) {
                    int cl = wn * 64 + nt * 8 + tg * 2 + e;
                    float v = fmaf(-2.f, acc[mt][nt][h * 2 + e], s_wsq[cl]);
                    ins3(v, kt * 128 + cl, t0, t1, t2, i0, i1, i2);
                }
#pragma unroll
            for (int off = 1; off <= 2; off <<= 1) {     // merge across 4-lane quad
                float o0 = __shfl_xor_sync(~0u, t0, off);
                float o1 = __shfl_xor_sync(~0u, t1, off);
                float o2 = __shfl_xor_sync(~0u, t2, off);
                int   a0 = __shfl_xor_sync(~0u, i0, off);
                int   a1 = __shfl_xor_sync(~0u, i1, off);
                int   a2 = __shfl_xor_sync(~0u, i2, off);
                ins3(o0, a0, t0, t1, t2, i0, i1, i2);
                ins3(o1, a1, t0, t1, t2, i0, i1, i2);
                ins3(o2, a2, t0, t1, t2, i0, i1, i2);
            }
            if (tg == 0) {
                int rl = wm * 32 + mt * 16 + g + h * 8;
                s_tv[rl][wn * 3]     = t0; s_ti[rl][wn * 3]     = i0;
                s_tv[rl][wn * 3 + 1] = t1; s_ti[rl][wn * 3 + 1] = i1;
                s_tv[rl][wn * 3 + 2] = t2; s_ti[rl][wn * 3 + 2] = i2;
            }
        }
    __syncthreads();

    if (tid < 128) {
        float t0 = 3.4e38f, t1 = 3.4e38f, t2 = 3.4e38f;
        int   i0 = 0, i1 = 0, i2 = 0;
#pragma unroll
        for (int j = 0; j < 6; j++) ins3(s_tv[tid][j], s_ti[tid][j], t0, t1, t2, i0, i1, i2);
        int row = f * B_ + row0 + tid;
        int b = row * 24 + kt * 3;
        g_cval[b] = t0; g_cval[b + 1] = t1; g_cval[b + 2] = t2;
        g_cidx[b] = i0; g_cidx[b + 1] = i1; g_cidx[b + 2] = i2;
    }
}

// ---------------- kernel 5: exact rescore + straight-through out + loss ----------------
__global__ void __launch_bounds__(256) k_rescore(const float* __restrict__ x,
                                                 float* __restrict__ out) {
    __shared__ float red[8];
    const int tid = threadIdx.x, lane = tid & 31, wid = tid >> 5;
    const int row = blockIdx.x * 8 + wid;
    const int f = row >> 12;

    float cv = 3.4e38f; int ci = 0;
    if (lane < 24) { cv = g_cval[row * 24 + lane]; ci = g_cidx[row * 24 + lane]; }
    float minv = cv;
#pragma unroll
    for (int o = 16; o >= 1; o >>= 1) minv = fminf(minv, __shfl_xor_sync(~0u, minv, o));
    const float gate = minv + 0.05f;   // ~10 sigma of bf16 screen error

    const float4* x4 = reinterpret_cast<const float4*>(x + (size_t)row * D_);
    const float4 xa = x4[lane], xb2 = x4[lane + 32];

    float bs = 3.4e38f; int bi = 0;
#pragma unroll 1
    for (int j = 0; j < 24; j++) {
        float vj = __shfl_sync(~0u, cv, j);
        int   ij = __shfl_sync(~0u, ci, j);
        if (vj <= gate) {                       // warp-uniform
            const float4* q4 = reinterpret_cast<const float4*>(g_wt + (size_t)(f * K_ + ij) * D_);
            float4 qa = q4[lane], qb = q4[lane + 32];
            float p = xa.x * qa.x;
            p = fmaf(xa.y, qa.y, p);  p = fmaf(xa.z, qa.z, p);  p = fmaf(xa.w, qa.w, p);
            p = fmaf(xb2.x, qb.x, p); p = fmaf(xb2.y, qb.y, p);
            p = fmaf(xb2.z, qb.z, p); p = fmaf(xb2.w, qb.w, p);
#pragma unroll
            for (int o = 16; o >= 1; o >>= 1) p += __shfl_xor_sync(~0u, p, o);
            float s = fmaf(-2.f, p, g_wsq[f * K_ + ij]);
            if (s < bs || (s == bs && ij < bi)) { bs = s; bi = ij; }   // first-index tie rule
        }
    }

    const float4* q4 = reinterpret_cast<const float4*>(g_wt + (size_t)(f * K_ + bi) * D_);
    float ls = 0.f;
    {
        float4 q = q4[lane];
        float d0 = q.x - xa.x, d1 = q.y - xa.y, d2 = q.z - xa.z, d3 = q.w - xa.w;
        float4 o; o.x = xa.x + d0; o.y = xa.y + d1; o.z = xa.z + d2; o.w = xa.w + d3;
        reinterpret_cast<float4*>(out)[(size_t)row * 64 + lane] = o;
        ls += d0 * d0 + d1 * d1 + d2 * d2 + d3 * d3;
    }
    {
        float4 q = q4[lane + 32];
        float d0 = q.x - xb2.x, d1 = q.y - xb2.y, d2 = q.z - xb2.z, d3 = q.w - xb2.w;
        float4 o; o.x = xb2.x + d0; o.y = xb2.y + d1; o.z = xb2.z + d2; o.w = xb2.w + d3;
        reinterpret_cast<float4*>(out)[(size_t)row * 64 + lane + 32] = o;
        ls += d0 * d0 + d1 * d1 + d2 * d2 + d3 * d3;
    }
#pragma unroll
    for (int o = 16; o >= 1; o >>= 1) ls += __shfl_xor_sync(~0u, ls, o);
    if (lane == 0) red[wid] = ls;
    __syncthreads();
    if (tid == 0) {
        float s = 0.f;
#pragma unroll
        for (int i = 0; i < 8; i++) s += red[i];
        g_part[blockIdx.x] = s;
    }
}

// ---------------- kernel 6: deterministic final loss ----------------
__global__ void k_loss(float* __restrict__ out) {
    __shared__ float red[256];
    const int tid = threadIdx.x;
    float s = 0.f;
#pragma unroll
    for (int i = 0; i < 32; i++) s += g_part[tid + 256 * i];
    red[tid] = s;
    __syncthreads();
    for (int st = 128; st > 0; st >>= 1) {
        if (tid < st) red[tid] += red[tid + st];
        __syncthreads();
    }
    if (tid == 0)
        out[(size_t)F_ * B_ * D_] = red[0] * (0.25f / (float)(F_ * B_ * D_));
}

extern "C" void kernel_launch(void* const* d_in, const int* in_sizes, int n_in,
                              void* d_out, int out_size) {
    const float* x = (const float*)d_in[0];   // [F,B,D] fp32
    const float* w = (const float*)d_in[1];   // [F,D,K] fp32
    float* out = (float*)d_out;
    (void)in_sizes; (void)n_in; (void)out_size;

    k_xbf<<<(F_ * B_ * D_) / 4 / 256, 256>>>(x);
    k_transpose<<<dim3(K_ / 32, D_ / 32, F_), dim3(32, 8)>>>(w);
    k_wsq<<<(F_ * K_) / 256, 256>>>(w);

    cudaFuncSetAttribute(k_screen, cudaFuncAttributeMaxDynamicSharedMemorySize, 66560);
    k_screen<<<dim3(B_ / 128, K_ / 128, F_), 256, 66560>>>();

    k_rescore<<<(F_ * B_) / 8, 256>>>(x, out);
    k_loss<<<1, 256>>>(out);
}

// round 11
// speedup vs baseline: 3.9519x; 1.5946x over previous
#include <cuda_runtime.h>
#include <cuda_bf16.h>
#include <cstdint>

#define F_ 16
#define B_ 4096
#define D_ 256
#define K_ 1024

// ---------------- device scratch (allocation-free) ----------------
__device__ __align__(128) float         g_wt [F_ * K_ * D_];   // w^T fp32 [f][k][d]
__device__ __align__(128) __nv_bfloat16 g_wtb[F_ * K_ * D_];   // w^T bf16 [f][k][d]
__device__ __align__(128) __nv_bfloat16 g_xb [F_ * B_ * D_];   // x bf16   [f][b][d]
__device__ float    g_wsq [F_ * K_];       // ||w_k||^2
__device__ uint32_t g_ckey[F_ * B_ * 24];  // packed (score, code) candidate keys
__device__ float    g_part[8192];          // loss partials

// ---------------- PTX helpers ----------------
__device__ __forceinline__ uint32_t sm_u32(const void* p) {
    uint32_t a;
    asm("{ .reg .u64 t; cvta.to.shared.u64 t, %1; cvt.u32.u64 %0, t; }" : "=r"(a) : "l"(p));
    return a;
}
__device__ __forceinline__ void cp16(uint32_t saddr, const void* g) {
    asm volatile("cp.async.cg.shared.global [%0], [%1], 16;" :: "r"(saddr), "l"(g));
}
__device__ __forceinline__ void ldsm4(uint32_t* r, uint32_t a) {
    asm volatile("ldmatrix.sync.aligned.m8n8.x4.shared.b16 {%0,%1,%2,%3}, [%4];"
                 : "=r"(r[0]), "=r"(r[1]), "=r"(r[2]), "=r"(r[3]) : "r"(a));
}
__device__ __forceinline__ void mma16816(float* c, const uint32_t* a, const uint32_t* b) {
    asm volatile(
        "mma.sync.aligned.m16n8k16.row.col.f32.bf16.bf16.f32 "
        "{%0,%1,%2,%3}, {%4,%5,%6,%7}, {%8,%9}, {%0,%1,%2,%3};"
        : "+f"(c[0]), "+f"(c[1]), "+f"(c[2]), "+f"(c[3])
        : "r"(a[0]), "r"(a[1]), "r"(a[2]), "r"(a[3]), "r"(b[0]), "r"(b[1]));
}
// ---- packed (score, index) keys: monotonic float->u32, low 10 bits = code idx ----
__device__ __forceinline__ uint32_t packkey(float v, int kk) {
    uint32_t s = __float_as_uint(v);
    uint32_t u = s ^ ((uint32_t)((int)s >> 31) | 0x80000000u);
    return (u & 0xFFFFFC00u) | (uint32_t)kk;
}
__device__ __forceinline__ float unpackval(uint32_t key) {
    uint32_t u = key & 0xFFFFFC00u;
    uint32_t s = (u & 0x80000000u) ? (u ^ 0x80000000u) : ~u;
    return __uint_as_float(s);
}
// branchless sorted top-3 insert (ascending): 5 u32 min/max
__device__ __forceinline__ void kins3(uint32_t k, uint32_t& t0, uint32_t& t1, uint32_t& t2) {
    uint32_t m0 = max(t0, k); t0 = min(t0, k);
    uint32_t m1 = max(t1, m0); t1 = min(t1, m0);
    t2 = min(t2, m1);
}

// ---------------- kernel 1: x -> bf16 ----------------
__global__ void k_xbf(const float* __restrict__ x) {
    int i = blockIdx.x * 256 + threadIdx.x;
    float4 v = reinterpret_cast<const float4*>(x)[i];
    __nv_bfloat162 h0 = __floats2bfloat162_rn(v.x, v.y);
    __nv_bfloat162 h1 = __floats2bfloat162_rn(v.z, v.w);
    uint2 u;
    u.x = *reinterpret_cast<uint32_t*>(&h0);
    u.y = *reinterpret_cast<uint32_t*>(&h1);
    reinterpret_cast<uint2*>(g_xb)[i] = u;
}

// ---------------- kernel 2: transpose w[f][d][k] -> wt (fp32 + bf16) ----------------
__global__ void k_transpose(const float* __restrict__ w) {
    __shared__ float t[32][33];
    const int f = blockIdx.z, k0 = blockIdx.x * 32, d0 = blockIdx.y * 32;
    const int tx = threadIdx.x, ty = threadIdx.y;   // 32 x 8
    const float* wf = w + (size_t)f * D_ * K_;
#pragma unroll
    for (int i = 0; i < 4; i++) {
        int d = d0 + ty + i * 8;
        t[ty + i * 8][tx] = wf[(size_t)d * K_ + k0 + tx];
    }
    __syncthreads();
    float*         wtf  = g_wt  + (size_t)f * K_ * D_;
    __nv_bfloat16* wtbf = g_wtb + (size_t)f * K_ * D_;
#pragma unroll
    for (int i = 0; i < 4; i++) {
        int k = k0 + ty + i * 8;
        float v = t[tx][ty + i * 8];
        wtf [(size_t)k * D_ + d0 + tx] = v;
        wtbf[(size_t)k * D_ + d0 + tx] = __float2bfloat16(v);
    }
}

// ---------------- kernel 3: wsq ----------------
__global__ void k_wsq(const float* __restrict__ w) {
    int t = blockIdx.x * 256 + threadIdx.x;
    int f = t >> 10, k = t & (K_ - 1);
    const float* p = w + (size_t)f * D_ * K_ + k;
    float s = 0.f;
#pragma unroll 8
    for (int d = 0; d < D_; d++) {
        float v = p[(size_t)d * K_];
        s = fmaf(v, v, s);
    }
    g_wsq[t] = s;
}

// ---------------- kernel 4: bf16 mma.sync screen, top-3 per 128-code tile ----------------
// Grid (B/128, K/128, F) = (32, 8, 16). Block 256 (8 warps, 4x2 grid, warp tile
// 32x64). 2 CTAs/SM. S[128 rows][128 codes] over K=D=256, 4 d-chunks of 64,
// double-buffered cp.async. SMEM swizzle: addr = r*128 + (colByte ^ ((r&7)<<4)).
// Epilogue is fully branchless on packed u32 keys.
__global__ void __launch_bounds__(256, 2) k_screen() {
    extern __shared__ __align__(128) char dsm[];
    __shared__ float    s_wsq[128];
    __shared__ uint32_t s_tk[128][6];

    const int tid = threadIdx.x, lane = tid & 31, wid = tid >> 5;
    const int wm = wid >> 1, wn = wid & 1;
    const int g = lane >> 2, tg = lane & 3;
    const int f = blockIdx.z, kt = blockIdx.y, row0 = blockIdx.x * 128;

    const uint32_t aS = (sm_u32(dsm) + 1023u) & ~1023u;   // [2][128 rows][64 d] bf16
    const uint32_t bS = aS + 32768u;                      // [2][128 codes][64 d] bf16

    if (tid < 128) s_wsq[tid] = g_wsq[f * K_ + kt * 128 + tid];

    const char* xg = (const char*)g_xb  + (size_t)(f * B_ + row0)      * 512;
    const char* wg = (const char*)g_wtb + (size_t)(f * K_ + kt * 128)  * 512;

    auto issue = [&](int c) {
        uint32_t ab = aS + (uint32_t)(c & 1) * 16384u;
        uint32_t bb = bS + (uint32_t)(c & 1) * 16384u;
#pragma unroll
        for (int i = 0; i < 4; i++) {                    // A: 1024 x 16B
            int t = tid + i * 256, r = t >> 3, cc = t & 7;
            cp16(ab + (uint32_t)(r * 128 + ((cc * 16) ^ ((r & 7) << 4))),
                 xg + (size_t)r * 512 + c * 128 + cc * 16);
        }
#pragma unroll
        for (int i = 0; i < 4; i++) {                    // B: 1024 x 16B
            int t = tid + i * 256, r = t >> 3, cc = t & 7;
            cp16(bb + (uint32_t)(r * 128 + ((cc * 16) ^ ((r & 7) << 4))),
                 wg + (size_t)r * 512 + c * 128 + cc * 16);
        }
        asm volatile("cp.async.commit_group;");
    };

    issue(0);
    issue(1);

    // per-lane ldmatrix constants: addr = base + rowBase + ((klb + laneCol) ^ rowSw)
    uint32_t aBase[2], aSw[2], bBase[4], bSw[4];
    const uint32_t aCol = (uint32_t)((lane >> 4) << 4);          // 0 | 16
    const uint32_t bCol = (uint32_t)(((lane >> 3) & 1) << 4);    // 0 | 16
#pragma unroll
    for (int mt = 0; mt < 2; mt++) {
        int r = wm * 32 + mt * 16 + (lane & 15);
        aBase[mt] = (uint32_t)(r * 128);
        aSw[mt]   = (uint32_t)((r & 7) << 4);
    }
#pragma unroll
    for (int nt2 = 0; nt2 < 4; nt2++) {
        int r = wn * 64 + nt2 * 16 + (lane & 7) + ((lane >> 4) << 3);
        bBase[nt2] = (uint32_t)(r * 128);
        bSw[nt2]   = (uint32_t)((r & 7) << 4);
    }

    float acc[2][8][4];
#pragma unroll
    for (int mt = 0; mt < 2; mt++)
#pragma unroll
        for (int nt = 0; nt < 8; nt++)
#pragma unroll
            for (int j = 0; j < 4; j++) acc[mt][nt][j] = 0.f;

    for (int c = 0; c < 4; c++) {
        if (c == 3) asm volatile("cp.async.wait_group 0;");
        else        asm volatile("cp.async.wait_group 1;");
        __syncthreads();
        uint32_t ab = aS + (uint32_t)(c & 1) * 16384u;
        uint32_t bb = bS + (uint32_t)(c & 1) * 16384u;
#pragma unroll
        for (int ks = 0; ks < 4; ks++) {
            uint32_t klb = (uint32_t)(ks * 32);          // k-step * 16 elems * 2B
            uint32_t a[2][4], b[4][4];
#pragma unroll
            for (int mt = 0; mt < 2; mt++)
                ldsm4(a[mt], ab + aBase[mt] + ((klb + aCol) ^ aSw[mt]));
#pragma unroll
            for (int nt2 = 0; nt2 < 4; nt2++)
                ldsm4(b[nt2], bb + bBase[nt2] + ((klb + bCol) ^ bSw[nt2]));
#pragma unroll
            for (int mt = 0; mt < 2; mt++)
#pragma unroll
                for (int nt2 = 0; nt2 < 4; nt2++) {
                    mma16816(acc[mt][nt2 * 2],     a[mt], &b[nt2][0]);
                    mma16816(acc[mt][nt2 * 2 + 1], a[mt], &b[nt2][2]);
                }
        }
        __syncthreads();
        if (c + 2 < 4) issue(c + 2);
    }

    // Branchless epilogue: v = wsq - 2*xw ; packed-key top-3 per row per tile.
#pragma unroll
    for (int mt = 0; mt < 2; mt++)
#pragma unroll
        for (int h = 0; h < 2; h++) {
            uint32_t t0 = 0xFFFFFFFFu, t1 = 0xFFFFFFFFu, t2 = 0xFFFFFFFFu;
#pragma unroll
            for (int nt = 0; nt < 8; nt++)
#pragma unroll
                for (int e = 0; e < 2; e++) {
                    int cl = wn * 64 + nt * 8 + tg * 2 + e;
                    float v = fmaf(-2.f, acc[mt][nt][h * 2 + e], s_wsq[cl]);
                    kins3(packkey(v, kt * 128 + cl), t0, t1, t2);
                }
#pragma unroll
            for (int off = 1; off <= 2; off <<= 1) {     // merge across 4-lane quad
                uint32_t o0 = __shfl_xor_sync(~0u, t0, off);
                uint32_t o1 = __shfl_xor_sync(~0u, t1, off);
                uint32_t o2 = __shfl_xor_sync(~0u, t2, off);
                kins3(o0, t0, t1, t2);
                kins3(o1, t0, t1, t2);
                kins3(o2, t0, t1, t2);
            }
            if (tg == 0) {
                int rl = wm * 32 + mt * 16 + g + h * 8;
                s_tk[rl][wn * 3]     = t0;
                s_tk[rl][wn * 3 + 1] = t1;
                s_tk[rl][wn * 3 + 2] = t2;
            }
        }
    __syncthreads();

    if (tid < 128) {
        uint32_t t0 = 0xFFFFFFFFu, t1 = 0xFFFFFFFFu, t2 = 0xFFFFFFFFu;
#pragma unroll
        for (int j = 0; j < 6; j++) kins3(s_tk[tid][j], t0, t1, t2);
        int row = f * B_ + row0 + tid;
        int b = row * 24 + kt * 3;
        g_ckey[b] = t0; g_ckey[b + 1] = t1; g_ckey[b + 2] = t2;
    }
}

// ---------------- kernel 5: exact rescore + straight-through out + loss ----------------
__global__ void __launch_bounds__(256) k_rescore(const float* __restrict__ x,
                                                 float* __restrict__ out) {
    __shared__ float red[8];
    const int tid = threadIdx.x, lane = tid & 31, wid = tid >> 5;
    const int row = blockIdx.x * 8 + wid;
    const int f = row >> 12;

    uint32_t key = 0xFFFFFFFFu;
    if (lane < 24) key = g_ckey[row * 24 + lane];
    uint32_t kmin = key;
#pragma unroll
    for (int o = 16; o >= 1; o >>= 1) kmin = min(kmin, __shfl_xor_sync(~0u, kmin, o));
    const float gate = unpackval(kmin) + 0.05f;   // ~10 sigma of bf16 screen error

    const float4* x4 = reinterpret_cast<const float4*>(x + (size_t)row * D_);
    const float4 xa = x4[lane], xb2 = x4[lane + 32];

    float bs = 3.4e38f; int bi = 0;
#pragma unroll 1
    for (int j = 0; j < 24; j++) {
        uint32_t kj = __shfl_sync(~0u, key, j);
        float vj = unpackval(kj);
        int   ij = (int)(kj & 1023u);
        if (vj <= gate) {                       // warp-uniform
            const float4* q4 = reinterpret_cast<const float4*>(g_wt + (size_t)(f * K_ + ij) * D_);
            float4 qa = q4[lane], qb = q4[lane + 32];
            float p = xa.x * qa.x;
            p = fmaf(xa.y, qa.y, p);  p = fmaf(xa.z, qa.z, p);  p = fmaf(xa.w, qa.w, p);
            p = fmaf(xb2.x, qb.x, p); p = fmaf(xb2.y, qb.y, p);
            p = fmaf(xb2.z, qb.z, p); p = fmaf(xb2.w, qb.w, p);
#pragma unroll
            for (int o = 16; o >= 1; o >>= 1) p += __shfl_xor_sync(~0u, p, o);
            float s = fmaf(-2.f, p, g_wsq[f * K_ + ij]);
            if (s < bs || (s == bs && ij < bi)) { bs = s; bi = ij; }   // first-index tie rule
        }
    }

    const float4* q4 = reinterpret_cast<const float4*>(g_wt + (size_t)(f * K_ + bi) * D_);
    float ls = 0.f;
    {
        float4 q = q4[lane];
        float d0 = q.x - xa.x, d1 = q.y - xa.y, d2 = q.z - xa.z, d3 = q.w - xa.w;
        float4 o; o.x = xa.x + d0; o.y = xa.y + d1; o.z = xa.z + d2; o.w = xa.w + d3;
        reinterpret_cast<float4*>(out)[(size_t)row * 64 + lane] = o;
        ls += d0 * d0 + d1 * d1 + d2 * d2 + d3 * d3;
    }
    {
        float4 q = q4[lane + 32];
        float d0 = q.x - xb2.x, d1 = q.y - xb2.y, d2 = q.z - xb2.z, d3 = q.w - xb2.w;
        float4 o; o.x = xb2.x + d0; o.y = xb2.y + d1; o.z = xb2.z + d2; o.w = xb2.w + d3;
        reinterpret_cast<float4*>(out)[(size_t)row * 64 + lane + 32] = o;
        ls += d0 * d0 + d1 * d1 + d2 * d2 + d3 * d3;
    }
#pragma unroll
    for (int o = 16; o >= 1; o >>= 1) ls += __shfl_xor_sync(~0u, ls, o);
    if (lane == 0) red[wid] = ls;
    __syncthreads();
    if (tid == 0) {
        float s = 0.f;
#pragma unroll
        for (int i = 0; i < 8; i++) s += red[i];
        g_part[blockIdx.x] = s;
    }
}

// ---------------- kernel 6: deterministic final loss ----------------
__global__ void k_loss(float* __restrict__ out) {
    __shared__ float red[256];
    const int tid = threadIdx.x;
    float s = 0.f;
#pragma unroll
    for (int i = 0; i < 32; i++) s += g_part[tid + 256 * i];
    red[tid] = s;
    __syncthreads();
    for (int st = 128; st > 0; st >>= 1) {
        if (tid < st) red[tid] += red[tid + st];
        __syncthreads();
    }
    if (tid == 0)
        out[(size_t)F_ * B_ * D_] = red[0] * (0.25f / (float)(F_ * B_ * D_));
}

extern "C" void kernel_launch(void* const* d_in, const int* in_sizes, int n_in,
                              void* d_out, int out_size) {
    const float* x = (const float*)d_in[0];   // [F,B,D] fp32
    const float* w = (const float*)d_in[1];   // [F,D,K] fp32
    float* out = (float*)d_out;
    (void)in_sizes; (void)n_in; (void)out_size;

    k_xbf<<<(F_ * B_ * D_) / 4 / 256, 256>>>(x);
    k_transpose<<<dim3(K_ / 32, D_ / 32, F_), dim3(32, 8)>>>(w);
    k_wsq<<<(F_ * K_) / 256, 256>>>(w);

    cudaFuncSetAttribute(k_screen, cudaFuncAttributeMaxDynamicSharedMemorySize, 66560);
    k_screen<<<dim3(B_ / 128, K_ / 128, F_), 256, 66560>>>();

    k_rescore<<<(F_ * B_) / 8, 256>>>(x, out);
    k_loss<<<1, 256>>>(out);
}

// round 12
// speedup vs baseline: 4.0983x; 1.0370x over previous
#include <cuda_runtime.h>
#include <cuda_bf16.h>
#include <cstdint>

#define F_ 16
#define B_ 4096
#define D_ 256
#define K_ 1024

// ---------------- device scratch (allocation-free) ----------------
__device__ __align__(128) float         g_wt [F_ * K_ * D_];   // w^T fp32 [f][k][d]
__device__ __align__(128) __nv_bfloat16 g_wtb[F_ * K_ * D_];   // w^T bf16 [f][k][d]
__device__ __align__(128) __nv_bfloat16 g_xb [F_ * B_ * D_];   // x bf16   [f][b][d]
__device__ float    g_wsq [F_ * K_];       // ||w_k||^2
__device__ uint32_t g_ckey[F_ * B_ * 24];  // packed (score, code) candidate keys
__device__ float    g_part[8192];          // loss partials

// ---------------- PTX helpers ----------------
__device__ __forceinline__ uint32_t sm_u32(const void* p) {
    uint32_t a;
    asm("{ .reg .u64 t; cvta.to.shared.u64 t, %1; cvt.u32.u64 %0, t; }" : "=r"(a) : "l"(p));
    return a;
}
__device__ __forceinline__ void cp16(uint32_t saddr, const void* g) {
    asm volatile("cp.async.cg.shared.global [%0], [%1], 16;" :: "r"(saddr), "l"(g));
}
__device__ __forceinline__ void ldsm4(uint32_t* r, uint32_t a) {
    asm volatile("ldmatrix.sync.aligned.m8n8.x4.shared.b16 {%0,%1,%2,%3}, [%4];"
                 : "=r"(r[0]), "=r"(r[1]), "=r"(r[2]), "=r"(r[3]) : "r"(a));
}
__device__ __forceinline__ void mma16816(float* c, const uint32_t* a, const uint32_t* b) {
    asm volatile(
        "mma.sync.aligned.m16n8k16.row.col.f32.bf16.bf16.f32 "
        "{%0,%1,%2,%3}, {%4,%5,%6,%7}, {%8,%9}, {%0,%1,%2,%3};"
        : "+f"(c[0]), "+f"(c[1]), "+f"(c[2]), "+f"(c[3])
        : "r"(a[0]), "r"(a[1]), "r"(a[2]), "r"(a[3]), "r"(b[0]), "r"(b[1]));
}
// ---- packed (score, index) keys: monotonic float->u32, low 10 bits = code idx ----
__device__ __forceinline__ uint32_t packkey(float v, int kk) {
    uint32_t s = __float_as_uint(v);
    uint32_t u = s ^ ((uint32_t)((int)s >> 31) | 0x80000000u);
    return (u & 0xFFFFFC00u) | (uint32_t)kk;
}
__device__ __forceinline__ float unpackval(uint32_t key) {
    uint32_t u = key & 0xFFFFFC00u;
    uint32_t s = (u & 0x80000000u) ? (u ^ 0x80000000u) : ~u;
    return __uint_as_float(s);
}
// branchless sorted top-3 insert (ascending): 5 u32 min/max
__device__ __forceinline__ void kins3(uint32_t k, uint32_t& t0, uint32_t& t1, uint32_t& t2) {
    uint32_t m0 = max(t0, k); t0 = min(t0, k);
    uint32_t m1 = max(t1, m0); t1 = min(t1, m0);
    t2 = min(t2, m1);
}

// ---------------- kernel 1: x -> bf16 ----------------
__global__ void k_xbf(const float* __restrict__ x) {
    int i = blockIdx.x * 256 + threadIdx.x;
    float4 v = reinterpret_cast<const float4*>(x)[i];
    __nv_bfloat162 h0 = __floats2bfloat162_rn(v.x, v.y);
    __nv_bfloat162 h1 = __floats2bfloat162_rn(v.z, v.w);
    uint2 u;
    u.x = *reinterpret_cast<uint32_t*>(&h0);
    u.y = *reinterpret_cast<uint32_t*>(&h1);
    reinterpret_cast<uint2*>(g_xb)[i] = u;
}

// ---------------- kernel 2: transpose w[f][d][k] -> wt (fp32 + bf16) ----------------
__global__ void k_transpose(const float* __restrict__ w) {
    __shared__ float t[32][33];
    const int f = blockIdx.z, k0 = blockIdx.x * 32, d0 = blockIdx.y * 32;
    const int tx = threadIdx.x, ty = threadIdx.y;   // 32 x 8
    const float* wf = w + (size_t)f * D_ * K_;
#pragma unroll
    for (int i = 0; i < 4; i++) {
        int d = d0 + ty + i * 8;
        t[ty + i * 8][tx] = wf[(size_t)d * K_ + k0 + tx];
    }
    __syncthreads();
    float*         wtf  = g_wt  + (size_t)f * K_ * D_;
    __nv_bfloat16* wtbf = g_wtb + (size_t)f * K_ * D_;
#pragma unroll
    for (int i = 0; i < 4; i++) {
        int k = k0 + ty + i * 8;
        float v = t[tx][ty + i * 8];
        wtf [(size_t)k * D_ + d0 + tx] = v;
        wtbf[(size_t)k * D_ + d0 + tx] = __float2bfloat16(v);
    }
}

// ---------------- kernel 3: wsq ----------------
__global__ void k_wsq(const float* __restrict__ w) {
    int t = blockIdx.x * 256 + threadIdx.x;
    int f = t >> 10, k = t & (K_ - 1);
    const float* p = w + (size_t)f * D_ * K_ + k;
    float s = 0.f;
#pragma unroll 8
    for (int d = 0; d < D_; d++) {
        float v = p[(size_t)d * K_];
        s = fmaf(v, v, s);
    }
    g_wsq[t] = s;
}

// ---------------- kernel 4: bf16 mma.sync screen, top-3 per 128-code tile ----------------
// Grid (B/128, K/128, F) = (32, 8, 16). Block 256 (8 warps, 4x2 grid, warp tile
// 32x64). 2 CTAs/SM. S[128 rows][128 codes] over K=D=256, 4 d-chunks of 64.
// 3-stage cp.async pipeline (96KB smem): ONE sync per chunk; the reissue for
// chunk c+2 happens right after the sync (its buffer was consumed at c-1),
// before the chunk-c HMMA block, so loads overlap compute.
// SMEM swizzle: addr = r*128 + (colByte ^ ((r&7)<<4)).
__global__ void __launch_bounds__(256, 2) k_screen() {
    extern __shared__ __align__(128) char dsm[];
    __shared__ float    s_wsq[128];
    __shared__ uint32_t s_tk[128][6];

    const int tid = threadIdx.x, lane = tid & 31, wid = tid >> 5;
    const int wm = wid >> 1, wn = wid & 1;
    const int g = lane >> 2, tg = lane & 3;
    const int f = blockIdx.z, kt = blockIdx.y, row0 = blockIdx.x * 128;

    const uint32_t base = (sm_u32(dsm) + 1023u) & ~1023u;  // 3 x (A 16KB + B 16KB)

    if (tid < 128) s_wsq[tid] = g_wsq[f * K_ + kt * 128 + tid];

    const char* xg = (const char*)g_xb  + (size_t)(f * B_ + row0)      * 512;
    const char* wg = (const char*)g_wtb + (size_t)(f * K_ + kt * 128)  * 512;

    auto issue = [&](int c) {
        uint32_t ab = base + (uint32_t)(c % 3) * 32768u;
        uint32_t bb = ab + 16384u;
#pragma unroll
        for (int i = 0; i < 4; i++) {                    // A: 1024 x 16B
            int t = tid + i * 256, r = t >> 3, cc = t & 7;
            cp16(ab + (uint32_t)(r * 128 + ((cc * 16) ^ ((r & 7) << 4))),
                 xg + (size_t)r * 512 + c * 128 + cc * 16);
        }
#pragma unroll
        for (int i = 0; i < 4; i++) {                    // B: 1024 x 16B
            int t = tid + i * 256, r = t >> 3, cc = t & 7;
            cp16(bb + (uint32_t)(r * 128 + ((cc * 16) ^ ((r & 7) << 4))),
                 wg + (size_t)r * 512 + c * 128 + cc * 16);
        }
        asm volatile("cp.async.commit_group;");
    };

    issue(0);
    issue(1);

    // per-lane ldmatrix constants: addr = base + rowBase + ((klb + laneCol) ^ rowSw)
    uint32_t aBase[2], aSw[2], bBase[4], bSw[4];
    const uint32_t aCol = (uint32_t)((lane >> 4) << 4);          // 0 | 16
    const uint32_t bCol = (uint32_t)(((lane >> 3) & 1) << 4);    // 0 | 16
#pragma unroll
    for (int mt = 0; mt < 2; mt++) {
        int r = wm * 32 + mt * 16 + (lane & 15);
        aBase[mt] = (uint32_t)(r * 128);
        aSw[mt]   = (uint32_t)((r & 7) << 4);
    }
#pragma unroll
    for (int nt2 = 0; nt2 < 4; nt2++) {
        int r = wn * 64 + nt2 * 16 + (lane & 7) + ((lane >> 4) << 3);
        bBase[nt2] = (uint32_t)(r * 128);
        bSw[nt2]   = (uint32_t)((r & 7) << 4);
    }

    float acc[2][8][4];
#pragma unroll
    for (int mt = 0; mt < 2; mt++)
#pragma unroll
        for (int nt = 0; nt < 8; nt++)
#pragma unroll
            for (int j = 0; j < 4; j++) acc[mt][nt][j] = 0.f;

    for (int c = 0; c < 4; c++) {
        if (c == 3) asm volatile("cp.async.wait_group 0;");
        else        asm volatile("cp.async.wait_group 1;");
        __syncthreads();                                 // buffer c full for all warps
        if (c + 2 < 4) issue(c + 2);                     // buf (c+2)%3 consumed at c-1
        uint32_t ab = base + (uint32_t)(c % 3) * 32768u;
        uint32_t bb = ab + 16384u;
#pragma unroll
        for (int ks = 0; ks < 4; ks++) {
            uint32_t klb = (uint32_t)(ks * 32);          // k-step * 16 elems * 2B
            uint32_t a[2][4], b[4][4];
#pragma unroll
            for (int mt = 0; mt < 2; mt++)
                ldsm4(a[mt], ab + aBase[mt] + ((klb + aCol) ^ aSw[mt]));
#pragma unroll
            for (int nt2 = 0; nt2 < 4; nt2++)
                ldsm4(b[nt2], bb + bBase[nt2] + ((klb + bCol) ^ bSw[nt2]));
#pragma unroll
            for (int mt = 0; mt < 2; mt++)
#pragma unroll
                for (int nt2 = 0; nt2 < 4; nt2++) {
                    mma16816(acc[mt][nt2 * 2],     a[mt], &b[nt2][0]);
                    mma16816(acc[mt][nt2 * 2 + 1], a[mt], &b[nt2][2]);
                }
        }
    }

    // Branchless epilogue: v = wsq - 2*xw ; packed-key top-3 per row per tile.
#pragma unroll
    for (int mt = 0; mt < 2; mt++)
#pragma unroll
        for (int h = 0; h < 2; h++) {
            uint32_t t0 = 0xFFFFFFFFu, t1 = 0xFFFFFFFFu, t2 = 0xFFFFFFFFu;
#pragma unroll
            for (int nt = 0; nt < 8; nt++)
#pragma unroll
                for (int e = 0; e < 2; e++) {
                    int cl = wn * 64 + nt * 8 + tg * 2 + e;
                    float v = fmaf(-2.f, acc[mt][nt][h * 2 + e], s_wsq[cl]);
                    kins3(packkey(v, kt * 128 + cl), t0, t1, t2);
                }
#pragma unroll
            for (int off = 1; off <= 2; off <<= 1) {     // merge across 4-lane quad
                uint32_t o0 = __shfl_xor_sync(~0u, t0, off);
                uint32_t o1 = __shfl_xor_sync(~0u, t1, off);
                uint32_t o2 = __shfl_xor_sync(~0u, t2, off);
                kins3(o0, t0, t1, t2);
                kins3(o1, t0, t1, t2);
                kins3(o2, t0, t1, t2);
            }
            if (tg == 0) {
                int rl = wm * 32 + mt * 16 + g + h * 8;
                s_tk[rl][wn * 3]     = t0;
                s_tk[rl][wn * 3 + 1] = t1;
                s_tk[rl][wn * 3 + 2] = t2;
            }
        }
    __syncthreads();

    if (tid < 128) {
        uint32_t t0 = 0xFFFFFFFFu, t1 = 0xFFFFFFFFu, t2 = 0xFFFFFFFFu;
#pragma unroll
        for (int j = 0; j < 6; j++) kins3(s_tk[tid][j], t0, t1, t2);
        int row = f * B_ + row0 + tid;
        int b = row * 24 + kt * 3;
        g_ckey[b] = t0; g_ckey[b + 1] = t1; g_ckey[b + 2] = t2;
    }
}

// ---------------- kernel 5: exact rescore + straight-through out + loss ----------------
__global__ void __launch_bounds__(256) k_rescore(const float* __restrict__ x,
                                                 float* __restrict__ out) {
    __shared__ float red[8];
    const int tid = threadIdx.x, lane = tid & 31, wid = tid >> 5;
    const int row = blockIdx.x * 8 + wid;
    const int f = row >> 12;

    uint32_t key = 0xFFFFFFFFu;
    if (lane < 24) key = g_ckey[row * 24 + lane];
    uint32_t kmin = key;
#pragma unroll
    for (int o = 16; o >= 1; o >>= 1) kmin = min(kmin, __shfl_xor_sync(~0u, kmin, o));
    const float gate = unpackval(kmin) + 0.05f;   // ~10 sigma of bf16 screen error

    const float4* x4 = reinterpret_cast<const float4*>(x + (size_t)row * D_);
    const float4 xa = x4[lane], xb2 = x4[lane + 32];

    float bs = 3.4e38f; int bi = 0;
#pragma unroll 1
    for (int j = 0; j < 24; j++) {
        uint32_t kj = __shfl_sync(~0u, key, j);
        float vj = unpackval(kj);
        int   ij = (int)(kj & 1023u);
        if (vj <= gate) {                       // warp-uniform
            const float4* q4 = reinterpret_cast<const float4*>(g_wt + (size_t)(f * K_ + ij) * D_);
            float4 qa = q4[lane], qb = q4[lane + 32];
            float p = xa.x * qa.x;
            p = fmaf(xa.y, qa.y, p);  p = fmaf(xa.z, qa.z, p);  p = fmaf(xa.w, qa.w, p);
            p = fmaf(xb2.x, qb.x, p); p = fmaf(xb2.y, qb.y, p);
            p = fmaf(xb2.z, qb.z, p); p = fmaf(xb2.w, qb.w, p);
#pragma unroll
            for (int o = 16; o >= 1; o >>= 1) p += __shfl_xor_sync(~0u, p, o);
            float s = fmaf(-2.f, p, g_wsq[f * K_ + ij]);
            if (s < bs || (s == bs && ij < bi)) { bs = s; bi = ij; }   // first-index tie rule
        }
    }

    const float4* q4 = reinterpret_cast<const float4*>(g_wt + (size_t)(f * K_ + bi) * D_);
    float ls = 0.f;
    {
        float4 q = q4[lane];
        float d0 = q.x - xa.x, d1 = q.y - xa.y, d2 = q.z - xa.z, d3 = q.w - xa.w;
        float4 o; o.x = xa.x + d0; o.y = xa.y + d1; o.z = xa.z + d2; o.w = xa.w + d3;
        reinterpret_cast<float4*>(out)[(size_t)row * 64 + lane] = o;
        ls += d0 * d0 + d1 * d1 + d2 * d2 + d3 * d3;
    }
    {
        float4 q = q4[lane + 32];
        float d0 = q.x - xb2.x, d1 = q.y - xb2.y, d2 = q.z - xb2.z, d3 = q.w - xb2.w;
        float4 o; o.x = xb2.x + d0; o.y = xb2.y + d1; o.z = xb2.z + d2; o.w = xb2.w + d3;
        reinterpret_cast<float4*>(out)[(size_t)row * 64 + lane + 32] = o;
        ls += d0 * d0 + d1 * d1 + d2 * d2 + d3 * d3;
    }
#pragma unroll
    for (int o = 16; o >= 1; o >>= 1) ls += __shfl_xor_sync(~0u, ls, o);
    if (lane == 0) red[wid] = ls;
    __syncthreads();
    if (tid == 0) {
        float s = 0.f;
#pragma unroll
        for (int i = 0; i < 8; i++) s += red[i];
        g_part[blockIdx.x] = s;
    }
}

// ---------------- kernel 6: deterministic final loss ----------------
__global__ void k_loss(float* __restrict__ out) {
    __shared__ float red[256];
    const int tid = threadIdx.x;
    float s = 0.f;
#pragma unroll
    for (int i = 0; i < 32; i++) s += g_part[tid + 256 * i];
    red[tid] = s;
    __syncthreads();
    for (int st = 128; st > 0; st >>= 1) {
        if (tid < st) red[tid] += red[tid + st];
        __syncthreads();
    }
    if (tid == 0)
        out[(size_t)F_ * B_ * D_] = red[0] * (0.25f / (float)(F_ * B_ * D_));
}

extern "C" void kernel_launch(void* const* d_in, const int* in_sizes, int n_in,
                              void* d_out, int out_size) {
    const float* x = (const float*)d_in[0];   // [F,B,D] fp32
    const float* w = (const float*)d_in[1];   // [F,D,K] fp32
    float* out = (float*)d_out;
    (void)in_sizes; (void)n_in; (void)out_size;

    k_xbf<<<(F_ * B_ * D_) / 4 / 256, 256>>>(x);
    k_transpose<<<dim3(K_ / 32, D_ / 32, F_), dim3(32, 8)>>>(w);
    k_wsq<<<(F_ * K_) / 256, 256>>>(w);

    cudaFuncSetAttribute(k_screen, cudaFuncAttributeMaxDynamicSharedMemorySize, 99328);
    k_screen<<<dim3(B_ / 128, K_ / 128, F_), 256, 99328>>>();

    k_rescore<<<(F_ * B_) / 8, 256>>>(x, out);
    k_loss<<<1, 256>>>(out);
}